// round 11
// baseline (speedup 1.0000x reference)
#include <cuda_runtime.h>
#include <cuda_bf16.h>
#include <cstdint>

#define BATCH 8
#define SEQ   4096
#define DIN   1024
#define DH    1024
#define M_TOT (BATCH*SEQ)   // 32768

// tcgen05 exists only on arch-accelerated ('a') targets.
#if defined(__CUDA_ARCH_FEAT_SM103_ALL) || defined(__CUDA_ARCH_FEAT_SM100_ALL)
#define HAS_TC 1
#else
#define HAS_TC 0
#endif

// Scratch (device globals; no allocation allowed).
__device__ float         g_bbuf[(size_t)M_TOT*DH];      // 'b' coeffs; 'a' lives in d_out
__device__ __nv_bfloat16 g_xhi[(size_t)M_TOT*DIN];
__device__ __nv_bfloat16 g_xlo[(size_t)M_TOT*DIN];
__device__ __nv_bfloat16 g_wzhi[DH*DIN], g_wzlo[DH*DIN];
__device__ __nv_bfloat16 g_whhi[DH*DIN], g_whlo[DH*DIN];

// ---------------- common helpers ----------------
__device__ __forceinline__ uint32_t s2u(const void* p) {
    return (uint32_t)__cvta_generic_to_shared(p);
}
__device__ __forceinline__ void cp16(void* sdst, const void* gsrc) {
    asm volatile("cp.async.cg.shared.global [%0], [%1], 16;\n" :: "r"(s2u(sdst)), "l"(gsrc));
}
__device__ __forceinline__ void cp_commit() { asm volatile("cp.async.commit_group;\n"); }
template<int N> __device__ __forceinline__ void cp_wait() { asm volatile("cp.async.wait_group %0;\n" :: "n"(N)); }
__device__ __forceinline__ void fence_async_smem() {
    asm volatile("fence.proxy.async.shared::cta;" ::: "memory");
}

// Fused activation: a = sigmoid(-k) = 1-z ; b = z * g(pre)
__device__ __forceinline__ void act(float k, float p, float& a, float& bb) {
    float e  = expf(k);
    float ia = 1.f / (1.f + e);            // sigmoid(-k)
    a = ia;
    float z  = e * ia;                     // sigmoid(k)
    float gg = (p >= 0.f) ? (p + 0.5f) : (1.f / (1.f + expf(-p)));
    bb = z * gg;
}

// ================= split pass: fp32 -> bf16 hi + bf16 lo =================
__global__ void split_kernel(const float* __restrict__ src, int which, int n4) {
    int i = blockIdx.x * blockDim.x + threadIdx.x;
    if (i >= n4) return;
    __nv_bfloat16* hi = (which == 0) ? g_xhi : (which == 1) ? g_wzhi : g_whhi;
    __nv_bfloat16* lo = (which == 0) ? g_xlo : (which == 1) ? g_wzlo : g_whlo;
    float4 v = ((const float4*)src)[i];
    __nv_bfloat16 h0 = __float2bfloat16(v.x);
    __nv_bfloat16 h1 = __float2bfloat16(v.y);
    __nv_bfloat16 h2 = __float2bfloat16(v.z);
    __nv_bfloat16 h3 = __float2bfloat16(v.w);
    __nv_bfloat16 l0 = __float2bfloat16(v.x - __bfloat162float(h0));
    __nv_bfloat16 l1 = __float2bfloat16(v.y - __bfloat162float(h1));
    __nv_bfloat16 l2 = __float2bfloat16(v.z - __bfloat162float(h2));
    __nv_bfloat16 l3 = __float2bfloat16(v.w - __bfloat162float(h3));
    ((__nv_bfloat162*)hi)[2*i  ] = __nv_bfloat162(h0, h1);
    ((__nv_bfloat162*)hi)[2*i+1] = __nv_bfloat162(h2, h3);
    ((__nv_bfloat162*)lo)[2*i  ] = __nv_bfloat162(l0, l1);
    ((__nv_bfloat162*)lo)[2*i+1] = __nv_bfloat162(l2, l3);
}

// =====================================================================
// PATH A: cg1 tcgen05 GEMM, tile M=128 x N=128, BK=64 — round-5 kernel
// with ONE fix: producer-side fence.proxy.async.shared::cta after every
// cp.async.wait_group (generic->async proxy visibility for UTCHMMA reads).
// =====================================================================
#define KT       16             // 1024 / 64
#define ARR_B    16384          // 128 rows * 128B
#define STAGE_B  (6*ARR_B)      // Ahi,Alo,Wzhi,Wzlo,Whhi,Whlo
#define DSMEM_TC (2*STAGE_B + 1024)
#define IDESC_TC (0x490u | ((128u/8u)<<17) | ((128u/16u)<<24))   // bf16,f32,N=128,M=128

#if HAS_TC
__device__ __forceinline__ uint32_t elect_one() {
    uint32_t p;
    asm volatile("{\n\t.reg .pred p;\n\telect.sync _|p, 0xFFFFFFFF;\n\tselp.b32 %0,1,0,p;\n\t}" : "=r"(p));
    return p;
}
__device__ __forceinline__ void mbar_init(uint32_t mbar, uint32_t cnt) {
    asm volatile("mbarrier.init.shared.b64 [%0], %1;" :: "r"(mbar), "r"(cnt) : "memory");
}
__device__ __forceinline__ void mbar_wait(uint32_t mbar, uint32_t parity) {
    uint32_t done;
    do {
        asm volatile("{\n\t.reg .pred p;\n\t"
                     "mbarrier.try_wait.parity.acquire.cta.shared::cta.b64 p, [%1], %2, 0x989680;\n\t"
                     "selp.b32 %0,1,0,p;\n\t}"
                     : "=r"(done) : "r"(mbar), "r"(parity) : "memory");
    } while (!done);
}
__device__ __forceinline__ uint64_t mkdesc(uint32_t saddr) {
    // SW128 K-major: layout=2, version=1, SBO=64, LBO=1
    return 0x4000404000010000ULL | ((uint64_t)(saddr >> 4) & 0x3FFF);
}
__device__ __forceinline__ void mma_ss(uint32_t d, uint64_t a, uint64_t b, uint32_t idesc, uint32_t en) {
    asm volatile(
        "{\n\t.reg .pred p;\n\tsetp.ne.u32 p, %5, 0;\n\t"
        "tcgen05.mma.cta_group::1.kind::f16 [%0], %1, %2, %3, {%4,%4,%4,%4}, p;\n\t}"
        :: "r"(d), "l"(a), "l"(b), "r"(idesc), "r"(0u), "r"(en) : "memory");
}
__device__ __forceinline__ void tc_commit(uint32_t mbar) {
    asm volatile("tcgen05.commit.cta_group::1.mbarrier::arrive::one.shared::cluster.b64 [%0];"
                 :: "r"(mbar) : "memory");
}
#endif

__global__ __launch_bounds__(288, 1)
void gemm_act_tc(const float* __restrict__ bz, const float* __restrict__ bh,
                 float* __restrict__ Abuf /* = d_out */) {
#if HAS_TC
    extern __shared__ char dyn_smem[];
    __shared__ __align__(8) uint64_t s_free[2];
    __shared__ __align__(8) uint64_t s_done;
    __shared__ uint32_t s_tmem;

    char* sb = (char*)(((uintptr_t)dyn_smem + 1023) & ~(uintptr_t)1023);
    const int tid  = threadIdx.x;
    const int wid  = tid >> 5;
    const int lane = tid & 31;
    const int n0 = blockIdx.x * 128;
    const int m0 = blockIdx.y * 128;

    if (tid == 0) {
        mbar_init(s2u(&s_free[0]), 1);
        mbar_init(s2u(&s_free[1]), 1);
        mbar_init(s2u(&s_done), 1);
    }
    if (wid == 8) {
        asm volatile("tcgen05.alloc.cta_group::1.sync.aligned.shared::cta.b32 [%0], %1;"
                     :: "r"(s2u(&s_tmem)), "r"(256u) : "memory");
        asm volatile("tcgen05.relinquish_alloc_permit.cta_group::1.sync.aligned;");
    }
    __syncthreads();
    const uint32_t tb = s_tmem;

    // ---- loaders: 256 threads (warps 0-7), 24x16B per chunk ----
    auto load_chunk = [&](int c) {
        char* S = sb + (c & 1) * STAGE_B;
        int k0 = c * 64;
        #pragma unroll
        for (int i = 0; i < 4; i++) {
            int idx = tid + i * 256;            // 0..1023
            int row = idx >> 3;                 // 0..127
            int cg  = idx & 7;                  // 16B group
            uint32_t bo = (uint32_t)(row * 128 + cg * 16);
            uint32_t sw = bo ^ ((bo >> 3) & 0x70);
            int kk = k0 + cg * 8;
            size_t ga = (size_t)(m0 + row) * DIN + kk;
            size_t gb = (size_t)(n0 + row) * DIN + kk;
            cp16(S + 0*ARR_B + sw, &g_xhi [ga]);
            cp16(S + 1*ARR_B + sw, &g_xlo [ga]);
            cp16(S + 2*ARR_B + sw, &g_wzhi[gb]);
            cp16(S + 3*ARR_B + sw, &g_wzlo[gb]);
            cp16(S + 4*ARR_B + sw, &g_whhi[gb]);
            cp16(S + 5*ARR_B + sw, &g_whlo[gb]);
        }
        cp_commit();
    };

    if (wid < 8) { load_chunk(0); load_chunk(1); }

    for (int c = 0; c < KT; c++) {
        const int s = c & 1;
        if (wid < 8) {
            if (c < KT - 1) cp_wait<1>(); else cp_wait<0>();
            // FIX: producer-side generic->async proxy fence, every thread,
            // after completion of chunk c's cp.async writes, before the barrier.
            fence_async_smem();
        }
        __syncthreads();   // chunk c resident + fenced for the MMA warp

        if (wid == 8) {
            if (elect_one()) {
                fence_async_smem();
                char* S = sb + s * STAGE_B;
                uint64_t dAhi = mkdesc(s2u(S + 0*ARR_B));
                uint64_t dAlo = mkdesc(s2u(S + 1*ARR_B));
                uint64_t dZhi = mkdesc(s2u(S + 2*ARR_B));
                uint64_t dZlo = mkdesc(s2u(S + 3*ARR_B));
                uint64_t dHhi = mkdesc(s2u(S + 4*ARR_B));
                uint64_t dHlo = mkdesc(s2u(S + 5*ARR_B));
                #pragma unroll
                for (int ks = 0; ks < 4; ks++) {
                    uint64_t o = (uint64_t)(ks * 2);    // +32B per k16 step
                    uint32_t en0 = (c > 0 || ks > 0) ? 1u : 0u;
                    mma_ss(tb,       dAhi + o, dZhi + o, IDESC_TC, en0);
                    mma_ss(tb,       dAlo + o, dZhi + o, IDESC_TC, 1u);
                    mma_ss(tb,       dAhi + o, dZlo + o, IDESC_TC, 1u);
                    mma_ss(tb + 128, dAhi + o, dHhi + o, IDESC_TC, en0);
                    mma_ss(tb + 128, dAlo + o, dHhi + o, IDESC_TC, 1u);
                    mma_ss(tb + 128, dAhi + o, dHlo + o, IDESC_TC, 1u);
                }
                tc_commit(s2u(&s_free[s]));
                if (c == KT - 1) tc_commit(s2u(&s_done));
            }
        }

        if (wid < 8 && c + 2 < KT) {
            int cn = c + 2;
            int rn = cn >> 1;                          // >= 1
            mbar_wait(s2u(&s_free[cn & 1]), (uint32_t)((rn - 1) & 1));
            load_chunk(cn);
        }
    }

    // ---- wait all mma, then epilogue (warps 0-3 read TMEM) ----
    mbar_wait(s2u(&s_done), 0u);
    asm volatile("tcgen05.fence::after_thread_sync;" ::: "memory");

    if (wid < 4) {
        const int m = m0 + wid * 32 + lane;
        const size_t rowbase = (size_t)m * DH + n0;
        #pragma unroll
        for (int cb = 0; cb < 128; cb += 16) {
            uint32_t rz[16], rh[16];
            asm volatile(
                "tcgen05.ld.sync.aligned.32x32b.x16.b32 "
                "{%0,%1,%2,%3,%4,%5,%6,%7,%8,%9,%10,%11,%12,%13,%14,%15}, [%16];"
                : "=r"(rz[0]),"=r"(rz[1]),"=r"(rz[2]),"=r"(rz[3]),
                  "=r"(rz[4]),"=r"(rz[5]),"=r"(rz[6]),"=r"(rz[7]),
                  "=r"(rz[8]),"=r"(rz[9]),"=r"(rz[10]),"=r"(rz[11]),
                  "=r"(rz[12]),"=r"(rz[13]),"=r"(rz[14]),"=r"(rz[15])
                : "r"(tb + cb));
            asm volatile(
                "tcgen05.ld.sync.aligned.32x32b.x16.b32 "
                "{%0,%1,%2,%3,%4,%5,%6,%7,%8,%9,%10,%11,%12,%13,%14,%15}, [%16];"
                : "=r"(rh[0]),"=r"(rh[1]),"=r"(rh[2]),"=r"(rh[3]),
                  "=r"(rh[4]),"=r"(rh[5]),"=r"(rh[6]),"=r"(rh[7]),
                  "=r"(rh[8]),"=r"(rh[9]),"=r"(rh[10]),"=r"(rh[11]),
                  "=r"(rh[12]),"=r"(rh[13]),"=r"(rh[14]),"=r"(rh[15])
                : "r"(tb + 128 + cb));
            asm volatile("tcgen05.wait::ld.sync.aligned;" ::: "memory");
            #pragma unroll
            for (int q = 0; q < 4; q++) {
                float av[4], bv[4];
                #pragma unroll
                for (int j = 0; j < 4; j++) {
                    int idx = q * 4 + j;
                    int n = n0 + cb + idx;
                    float k = __uint_as_float(rz[idx]) + __ldg(&bz[n]);
                    float p = __uint_as_float(rh[idx]) + __ldg(&bh[n]);
                    act(k, p, av[j], bv[j]);
                }
                *(float4*)&Abuf  [rowbase + cb + q*4] = make_float4(av[0], av[1], av[2], av[3]);
                *(float4*)&g_bbuf[rowbase + cb + q*4] = make_float4(bv[0], bv[1], bv[2], bv[3]);
            }
        }
    }

    __syncthreads();
    if (wid == 8) {
        asm volatile("tcgen05.dealloc.cta_group::1.sync.aligned.b32 %0, %1;" :: "r"(tb), "r"(256u));
    }
#endif  // HAS_TC
}

// =====================================================================
// PATH B: legacy mma.sync GEMM (round-3, known-good) — non-'a' targets only.
// =====================================================================
#define BM 128
#define BN 64
#define BK 32
#define AST 40
#define STG_ELEMS 20480

#if !HAS_TC
__device__ __forceinline__ void mma_bf16(float d[4], const uint32_t a[4], uint32_t b0, uint32_t b1) {
    asm volatile(
        "mma.sync.aligned.m16n8k16.row.col.f32.bf16.bf16.f32 "
        "{%0,%1,%2,%3},{%4,%5,%6,%7},{%8,%9},{%0,%1,%2,%3};\n"
        : "+f"(d[0]), "+f"(d[1]), "+f"(d[2]), "+f"(d[3])
        : "r"(a[0]), "r"(a[1]), "r"(a[2]), "r"(a[3]), "r"(b0), "r"(b1));
}
#endif

__global__ __launch_bounds__(256, 2)
void gemm_act_legacy(const float* __restrict__ bz, const float* __restrict__ bh,
                     float* __restrict__ Abuf /* = d_out */) {
#if !HAS_TC
    extern __shared__ __nv_bfloat16 sm[];
    const int tid  = threadIdx.x;
    const int lane = tid & 31;
    const int wid  = tid >> 5;
    const int wm   = wid & 3;
    const int wn   = wid >> 2;
    const int g    = lane >> 2;
    const int t    = lane & 3;

    const int n0 = blockIdx.x * BN;
    const int m0 = blockIdx.y * BM;

    float accz[2][4][4], acch[2][4][4];
    #pragma unroll
    for (int i = 0; i < 2; i++)
        #pragma unroll
        for (int j = 0; j < 4; j++)
            #pragma unroll
            for (int r = 0; r < 4; r++) { accz[i][j][r] = 0.f; acch[i][j][r] = 0.f; }

    auto issue = [&](int kt, int buf) {
        int k0 = kt * BK;
        __nv_bfloat16* S = sm + buf * STG_ELEMS;
        #pragma unroll
        for (int i = 0; i < 2; i++) {
            int idx = tid + i * 256;
            int row = idx >> 2;
            int cg  = idx & 3;
            cp16(&S[row*AST + cg*8],        &g_xhi[(size_t)(m0+row)*DIN + k0 + cg*8]);
            cp16(&S[5120 + row*AST + cg*8], &g_xlo[(size_t)(m0+row)*DIN + k0 + cg*8]);
        }
        {
            int row = tid >> 2;
            int cg  = tid & 3;
            size_t go = (size_t)(n0+row)*DIN + k0 + cg*8;
            cp16(&S[10240 + row*AST + cg*8], &g_wzhi[go]);
            cp16(&S[12800 + row*AST + cg*8], &g_wzlo[go]);
            cp16(&S[15360 + row*AST + cg*8], &g_whhi[go]);
            cp16(&S[17920 + row*AST + cg*8], &g_whlo[go]);
        }
        cp_commit();
    };

    auto ld32 = [&](const __nv_bfloat16* p) -> uint32_t {
        return *(const uint32_t*)p;
    };

    issue(0, 0);
    const int KTL = DIN / BK;
    for (int kt = 0; kt < KTL; kt++) {
        int buf = kt & 1;
        if (kt + 1 < KTL) { issue(kt + 1, buf ^ 1); cp_wait<1>(); }
        else              { cp_wait<0>(); }
        __syncthreads();
        const __nv_bfloat16* S = sm + buf * STG_ELEMS;
        #pragma unroll
        for (int ks = 0; ks < 2; ks++) {
            const int kb = ks * 16;
            uint32_t ahi[2][4], alo[2][4];
            #pragma unroll
            for (int mf = 0; mf < 2; mf++) {
                int r = wm*32 + mf*16;
                const __nv_bfloat16* A0 = S + (r+g  )*AST + kb + 2*t;
                const __nv_bfloat16* A1 = S + (r+g+8)*AST + kb + 2*t;
                ahi[mf][0] = ld32(A0);     ahi[mf][1] = ld32(A1);
                ahi[mf][2] = ld32(A0 + 8); ahi[mf][3] = ld32(A1 + 8);
                alo[mf][0] = ld32(A0 + 5120);     alo[mf][1] = ld32(A1 + 5120);
                alo[mf][2] = ld32(A0 + 5120 + 8); alo[mf][3] = ld32(A1 + 5120 + 8);
            }
            #pragma unroll
            for (int nf = 0; nf < 4; nf++) {
                int c = wn*32 + nf*8 + g;
                const __nv_bfloat16* B = S + c*AST + kb + 2*t;
                uint32_t zh0 = ld32(B + 10240), zh1 = ld32(B + 10240 + 8);
                uint32_t zl0 = ld32(B + 12800), zl1 = ld32(B + 12800 + 8);
                uint32_t hh0 = ld32(B + 15360), hh1 = ld32(B + 15360 + 8);
                uint32_t hl0 = ld32(B + 17920), hl1 = ld32(B + 17920 + 8);
                #pragma unroll
                for (int mf = 0; mf < 2; mf++) {
                    mma_bf16(accz[mf][nf], ahi[mf], zh0, zh1);
                    mma_bf16(accz[mf][nf], alo[mf], zh0, zh1);
                    mma_bf16(accz[mf][nf], ahi[mf], zl0, zl1);
                    mma_bf16(acch[mf][nf], ahi[mf], hh0, hh1);
                    mma_bf16(acch[mf][nf], alo[mf], hh0, hh1);
                    mma_bf16(acch[mf][nf], ahi[mf], hl0, hl1);
                }
            }
        }
        __syncthreads();
    }

    #pragma unroll
    for (int mf = 0; mf < 2; mf++) {
        #pragma unroll
        for (int nf = 0; nf < 4; nf++) {
            int m = m0 + wm*32 + mf*16 + g;
            int n = n0 + wn*32 + nf*8 + 2*t;
            float bz0 = bz[n], bz1 = bz[n+1];
            float bh0 = bh[n], bh1 = bh[n+1];
            float a0,b0v,a1,b1v,a2,b2v,a3,b3v;
            act(accz[mf][nf][0] + bz0, acch[mf][nf][0] + bh0, a0, b0v);
            act(accz[mf][nf][1] + bz1, acch[mf][nf][1] + bh1, a1, b1v);
            act(accz[mf][nf][2] + bz0, acch[mf][nf][2] + bh0, a2, b2v);
            act(accz[mf][nf][3] + bz1, acch[mf][nf][3] + bh1, a3, b3v);
            size_t o0 = (size_t)m     * DH + n;
            size_t o1 = (size_t)(m+8) * DH + n;
            *(float2*)&Abuf[o0]   = make_float2(a0, a1);
            *(float2*)&g_bbuf[o0] = make_float2(b0v, b1v);
            *(float2*)&Abuf[o1]   = make_float2(a2, a3);
            *(float2*)&g_bbuf[o1] = make_float2(b2v, b3v);
        }
    }
#endif  // !HAS_TC
}

// ================= Sequential scan: h_t = a_t*h_{t-1} + b_t (fp64 carry) ======
// BYTE-EXACT round-5 scan (passed at rel_err 7.78e-5).
#define SCT 32
#define NST 3
#define SCH 64

__global__ __launch_bounds__(64)
void scan_kernel(float* __restrict__ out) {
    extern __shared__ float sms[];
    const int tid = threadIdx.x;
    const int b   = blockIdx.x >> 4;
    const int h0  = (blockIdx.x & 15) * SCH;
    const size_t base = (size_t)b * SEQ * DH + h0;
    const float* Asrc = out;
    const float* Bsrc = g_bbuf;

    auto issue = [&](int s) {
        int slot = s % NST;
        int t0 = s * SCT;
        float* sa   = &sms[(slot*2 + 0) * SCT * SCH];
        float* sbuf = &sms[(slot*2 + 1) * SCT * SCH];
        #pragma unroll
        for (int j = 0; j < 8; j++) {
            int idx = tid + j * 64;
            int tt  = idx >> 4;
            int c   = idx & 15;
            cp16(&sa[tt*SCH + c*4],   &Asrc[base + (size_t)(t0+tt)*DH + c*4]);
            cp16(&sbuf[tt*SCH + c*4], &Bsrc[base + (size_t)(t0+tt)*DH + c*4]);
        }
        cp_commit();
    };

    issue(0); issue(1);
    double h = 0.5;
    const int NS = SEQ / SCT;
    for (int s = 0; s < NS; s++) {
        cp_wait<1>();
        __syncthreads();
        int slot = s % NST;
        const float* sa   = &sms[(slot*2 + 0) * SCT * SCH];
        const float* sbuf = &sms[(slot*2 + 1) * SCT * SCH];
        int t0 = s * SCT;
        #pragma unroll
        for (int tt = 0; tt < SCT; tt++) {
            double a  = (double)sa[tt*SCH + tid];
            double bb = (double)sbuf[tt*SCH + tid];
            h = fma(a, h, bb);
            out[base + (size_t)(t0+tt)*DH + tid] = (float)h;
        }
        __syncthreads();
        if (s + 2 < NS) issue(s + 2);
    }
}

// ================= launch =================
extern "C" void kernel_launch(void* const* d_in, const int* in_sizes, int n_in,
                              void* d_out, int out_size) {
    // Identify inputs BY SIZE: 33554432 -> x ; 1048576 -> Wz then Wh ; 1024 -> bz then bh.
    const float* x = nullptr; const float* Wz = nullptr; const float* Wh = nullptr;
    const float* bz = nullptr; const float* bh = nullptr;
    for (int i = 0; i < n_in; i++) {
        int sz = in_sizes[i];
        const float* p = (const float*)d_in[i];
        if      (sz == M_TOT * DIN) { x = p; }
        else if (sz == DH * DIN)    { if (!Wz) Wz = p; else Wh = p; }
        else if (sz == DH)          { if (!bz) bz = p; else bh = p; }
    }
    if (!x || !Wz || !Wh || !bz || !bh) {
        x  = (const float*)d_in[0];
        Wz = (const float*)d_in[1];
        bz = (const float*)d_in[2];
        Wh = (const float*)d_in[3];
        bh = (const float*)d_in[4];
    }
    float* out = (float*)d_out;

    // 1) split fp32 -> bf16 hi/lo
    {
        int n4x = M_TOT * DIN / 4;
        split_kernel<<<(n4x + 255) / 256, 256>>>(x, 0, n4x);
        int n4w = DH * DIN / 4;
        split_kernel<<<(n4w + 255) / 256, 256>>>(Wz, 1, n4w);
        split_kernel<<<(n4w + 255) / 256, 256>>>(Wh, 2, n4w);
    }

    // 2) dual GEMM + activation — both variants launched; exactly one has a body.
    cudaFuncSetAttribute(gemm_act_tc, cudaFuncAttributeMaxDynamicSharedMemorySize, DSMEM_TC);
    dim3 tgrid(DH / 128, M_TOT / 128);   // (8, 256), n fast -> A-slab L2 reuse
    gemm_act_tc<<<tgrid, 288, DSMEM_TC>>>(bz, bh, out);

    cudaFuncSetAttribute(gemm_act_legacy, cudaFuncAttributeMaxDynamicSharedMemorySize,
                         2 * STG_ELEMS * (int)sizeof(__nv_bfloat16));
    dim3 lgrid(DH / BN, M_TOT / BM);     // (16, 256)
    gemm_act_legacy<<<lgrid, 256, 2 * STG_ELEMS * sizeof(__nv_bfloat16)>>>(bz, bh, out);

    // 3) sequential scan (reads a from out, overwrites with h)
    scan_kernel<<<BATCH * (DH / SCH), SCH, NST * 2 * SCT * SCH * sizeof(float)>>>(out);
}

// round 15
// speedup vs baseline: 1.0458x; 1.0458x over previous
#include <cuda_runtime.h>
#include <cuda_bf16.h>
#include <cstdint>

#define BATCH 8
#define SEQ   4096
#define DIN   1024
#define DH    1024
#define M_TOT (BATCH*SEQ)   // 32768

// tcgen05 exists only on arch-accelerated ('a') targets.
#if defined(__CUDA_ARCH_FEAT_SM103_ALL) || defined(__CUDA_ARCH_FEAT_SM100_ALL)
#define HAS_TC 1
#else
#define HAS_TC 0
#endif

// Scratch (device globals; no allocation allowed).
// hi/lo arrays are stored in BLOCKED-SWIZZLED layout:
//   [rowblk (rows/128)][kchunk (16)] -> contiguous 16KB tile, SW128-swizzled inside.
__device__ float         g_bbuf[(size_t)M_TOT*DH];      // 'b' coeffs; 'a' lives in d_out
__device__ __nv_bfloat16 g_xhi[(size_t)M_TOT*DIN];
__device__ __nv_bfloat16 g_xlo[(size_t)M_TOT*DIN];
__device__ __nv_bfloat16 g_wzhi[DH*DIN], g_wzlo[DH*DIN];
__device__ __nv_bfloat16 g_whhi[DH*DIN], g_whlo[DH*DIN];

// ---------------- common helpers ----------------
__device__ __forceinline__ uint32_t s2u(const void* p) {
    return (uint32_t)__cvta_generic_to_shared(p);
}
__device__ __forceinline__ void cp16(void* sdst, const void* gsrc) {
    asm volatile("cp.async.cg.shared.global [%0], [%1], 16;\n" :: "r"(s2u(sdst)), "l"(gsrc));
}
__device__ __forceinline__ void cp_commit() { asm volatile("cp.async.commit_group;\n"); }
template<int N> __device__ __forceinline__ void cp_wait() { asm volatile("cp.async.wait_group %0;\n" :: "n"(N)); }

// Fused activation: a = sigmoid(-k) = 1-z ; b = z * g(pre)
__device__ __forceinline__ void act(float k, float p, float& a, float& bb) {
    float e  = expf(k);
    float ia = 1.f / (1.f + e);            // sigmoid(-k)
    a = ia;
    float z  = e * ia;                     // sigmoid(k)
    float gg = (p >= 0.f) ? (p + 0.5f) : (1.f / (1.f + expf(-p)));
    bb = z * gg;
}

// Blocked-swizzled element offset (bf16 elems) for row rowg, elem col ke.
__device__ __forceinline__ size_t blk_off_elem(int rowg, int ke) {
    int blk = rowg >> 7, r = rowg & 127;
    int kc  = ke >> 6;
    int cg  = (ke >> 3) & 7;
    uint32_t bo = (uint32_t)(r * 128 + cg * 16);
    uint32_t sw = bo ^ ((bo >> 3) & 0x70);
    return (((size_t)(blk * 16 + kc)) << 13) + (sw >> 1);
}

// ================= split pass: fp32 -> blocked-swizzled bf16 hi + lo =========
// One thread per 16B granule (8 values).
__global__ void split_kernel(const float* __restrict__ src, int which, int ngr) {
    int g = blockIdx.x * blockDim.x + threadIdx.x;
    if (g >= ngr) return;
    __nv_bfloat16* hi = (which == 0) ? g_xhi : (which == 1) ? g_wzhi : g_whhi;
    __nv_bfloat16* lo = (which == 0) ? g_xlo : (which == 1) ? g_wzlo : g_whlo;
    float4 v0 = ((const float4*)src)[2*g];
    float4 v1 = ((const float4*)src)[2*g + 1];
    float f[8] = {v0.x, v0.y, v0.z, v0.w, v1.x, v1.y, v1.z, v1.w};
    uint32_t hb[4], lb[4];
    #pragma unroll
    for (int i = 0; i < 4; i++) {
        __nv_bfloat16 h0 = __float2bfloat16(f[2*i]);
        __nv_bfloat16 h1 = __float2bfloat16(f[2*i+1]);
        __nv_bfloat16 l0 = __float2bfloat16(f[2*i]   - __bfloat162float(h0));
        __nv_bfloat16 l1 = __float2bfloat16(f[2*i+1] - __bfloat162float(h1));
        __nv_bfloat162 hp(h0, h1), lp(l0, l1);
        hb[i] = *(uint32_t*)&hp;
        lb[i] = *(uint32_t*)&lp;
    }
    uint32_t row = (uint32_t)g >> 7;    // DIN=1024 -> 128 granules per row
    uint32_t kg  = (uint32_t)g & 127;
    uint32_t kc  = kg >> 3;
    uint32_t cg  = kg & 7;
    uint32_t blk = row >> 7;
    uint32_t r   = row & 127;
    uint32_t bo  = r * 128 + cg * 16;
    uint32_t sw  = bo ^ ((bo >> 3) & 0x70);
    size_t dst = (((size_t)(blk * 16 + kc)) << 14) + sw;   // bytes
    *(uint4*)((char*)hi + dst) = make_uint4(hb[0], hb[1], hb[2], hb[3]);
    *(uint4*)((char*)lo + dst) = make_uint4(lb[0], lb[1], lb[2], lb[3]);
}

// =====================================================================
// PATH A: cg1 tcgen05 GEMM, tile M=128 x N=128, BK=64.
// Transport = cp.async.bulk (async proxy, background copy engine).
// Single elected thread runs expect_tx -> bulk -> wait_full -> MMA ->
// commit -> wait_free pipeline. No generic-proxy smem writes in loop.
// =====================================================================
#define KT       16             // 1024 / 64
#define ARR_B    16384          // one blocked tile: 128 rows * 128B
#define STAGE_B  (6*ARR_B)      // Ahi,Alo,Wzhi,Wzlo,Whhi,Whlo
#define DSMEM_TC (2*STAGE_B + 1024)
#define IDESC_TC (0x490u | ((128u/8u)<<17) | ((128u/16u)<<24))   // bf16,f32,N=128,M=128

#if HAS_TC
__device__ __forceinline__ uint32_t elect_one() {
    uint32_t p;
    asm volatile("{\n\t.reg .pred p;\n\telect.sync _|p, 0xFFFFFFFF;\n\tselp.b32 %0,1,0,p;\n\t}" : "=r"(p));
    return p;
}
__device__ __forceinline__ void mbar_init(uint32_t mbar, uint32_t cnt) {
    asm volatile("mbarrier.init.shared.b64 [%0], %1;" :: "r"(mbar), "r"(cnt) : "memory");
}
__device__ __forceinline__ void mbar_expect_tx(uint32_t mbar, uint32_t bytes) {
    asm volatile("mbarrier.arrive.expect_tx.shared.b64 _, [%0], %1;"
                 :: "r"(mbar), "r"(bytes) : "memory");
}
__device__ __forceinline__ void mbar_wait(uint32_t mbar, uint32_t parity) {
    uint32_t done;
    do {
        asm volatile("{\n\t.reg .pred p;\n\t"
                     "mbarrier.try_wait.parity.acquire.cta.shared::cta.b64 p, [%1], %2, 0x989680;\n\t"
                     "selp.b32 %0,1,0,p;\n\t}"
                     : "=r"(done) : "r"(mbar), "r"(parity) : "memory");
    } while (!done);
}
// 1D bulk async copy global->smem, completion via mbarrier (async proxy).
__device__ __forceinline__ void bulk_ld(uint32_t sdst, const void* gsrc, uint32_t bytes, uint32_t mbar) {
    asm volatile(
        "cp.async.bulk.shared::cluster.global.mbarrier::complete_tx::bytes [%0], [%1], %2, [%3];"
        :: "r"(sdst), "l"(gsrc), "r"(bytes), "r"(mbar) : "memory");
}
__device__ __forceinline__ uint64_t mkdesc(uint32_t saddr) {
    // SW128 K-major: layout=2, version=1, SBO=64, LBO=1
    return 0x4000404000010000ULL | ((uint64_t)(saddr >> 4) & 0x3FFF);
}
__device__ __forceinline__ void mma_ss(uint32_t d, uint64_t a, uint64_t b, uint32_t idesc, uint32_t en) {
    asm volatile(
        "{\n\t.reg .pred p;\n\tsetp.ne.u32 p, %5, 0;\n\t"
        "tcgen05.mma.cta_group::1.kind::f16 [%0], %1, %2, %3, {%4,%4,%4,%4}, p;\n\t}"
        :: "r"(d), "l"(a), "l"(b), "r"(idesc), "r"(0u), "r"(en) : "memory");
}
__device__ __forceinline__ void tc_commit(uint32_t mbar) {
    asm volatile("tcgen05.commit.cta_group::1.mbarrier::arrive::one.shared::cluster.b64 [%0];"
                 :: "r"(mbar) : "memory");
}
#endif

__global__ __launch_bounds__(288, 1)
void gemm_act_tc(const float* __restrict__ bz, const float* __restrict__ bh,
                 float* __restrict__ Abuf /* = d_out */) {
#if HAS_TC
    extern __shared__ char dyn_smem[];
    __shared__ __align__(8) uint64_t s_full[2];
    __shared__ __align__(8) uint64_t s_free[2];
    __shared__ __align__(8) uint64_t s_done;
    __shared__ uint32_t s_tmem;

    char* sb = (char*)(((uintptr_t)dyn_smem + 1023) & ~(uintptr_t)1023);
    const int tid  = threadIdx.x;
    const int wid  = tid >> 5;
    const int lane = tid & 31;
    const int bn = blockIdx.x;          // n-block 0..7
    const int bm = blockIdx.y;          // m-block 0..255
    const int n0 = bn * 128;
    const int m0 = bm * 128;

    if (tid == 0) {
        mbar_init(s2u(&s_full[0]), 1);
        mbar_init(s2u(&s_full[1]), 1);
        mbar_init(s2u(&s_free[0]), 1);
        mbar_init(s2u(&s_free[1]), 1);
        mbar_init(s2u(&s_done), 1);
    }
    if (wid == 8) {
        asm volatile("tcgen05.alloc.cta_group::1.sync.aligned.shared::cta.b32 [%0], %1;"
                     :: "r"(s2u(&s_tmem)), "r"(256u) : "memory");
        asm volatile("tcgen05.relinquish_alloc_permit.cta_group::1.sync.aligned;");
    }
    __syncthreads();
    const uint32_t tb = s_tmem;

    // ---------------- single-thread pipeline (warp 8) ----------------
    if (wid == 8 && elect_one()) {
        auto load_chunk = [&](int c) {
            int s = c & 1;
            uint32_t mb = s2u(&s_full[s]);
            mbar_expect_tx(mb, (uint32_t)STAGE_B);
            uint32_t S = s2u(sb + s * STAGE_B);
            size_t xt = ((size_t)(bm * 16 + c)) << 14;   // X tile byte offset
            size_t wt = ((size_t)(bn * 16 + c)) << 14;   // W tile byte offset
            bulk_ld(S + 0*ARR_B, (const char*)g_xhi  + xt, ARR_B, mb);
            bulk_ld(S + 1*ARR_B, (const char*)g_xlo  + xt, ARR_B, mb);
            bulk_ld(S + 2*ARR_B, (const char*)g_wzhi + wt, ARR_B, mb);
            bulk_ld(S + 3*ARR_B, (const char*)g_wzlo + wt, ARR_B, mb);
            bulk_ld(S + 4*ARR_B, (const char*)g_whhi + wt, ARR_B, mb);
            bulk_ld(S + 5*ARR_B, (const char*)g_whlo + wt, ARR_B, mb);
        };

        load_chunk(0);
        load_chunk(1);

        for (int c = 0; c < KT; c++) {
            const int s = c & 1;
            const int r = c >> 1;
            mbar_wait(s2u(&s_full[s]), (uint32_t)(r & 1));   // chunk c resident

            char* S = sb + s * STAGE_B;
            uint64_t dAhi = mkdesc(s2u(S + 0*ARR_B));
            uint64_t dAlo = mkdesc(s2u(S + 1*ARR_B));
            uint64_t dZhi = mkdesc(s2u(S + 2*ARR_B));
            uint64_t dZlo = mkdesc(s2u(S + 3*ARR_B));
            uint64_t dHhi = mkdesc(s2u(S + 4*ARR_B));
            uint64_t dHlo = mkdesc(s2u(S + 5*ARR_B));
            #pragma unroll
            for (int ks = 0; ks < 4; ks++) {
                uint64_t o = (uint64_t)(ks * 2);    // +32B per k16 step
                uint32_t en0 = (c > 0 || ks > 0) ? 1u : 0u;
                mma_ss(tb,       dAhi + o, dZhi + o, IDESC_TC, en0);
                mma_ss(tb,       dAlo + o, dZhi + o, IDESC_TC, 1u);
                mma_ss(tb,       dAhi + o, dZlo + o, IDESC_TC, 1u);
                mma_ss(tb + 128, dAhi + o, dHhi + o, IDESC_TC, en0);
                mma_ss(tb + 128, dAlo + o, dHhi + o, IDESC_TC, 1u);
                mma_ss(tb + 128, dAhi + o, dHlo + o, IDESC_TC, 1u);
            }
            tc_commit(s2u(&s_free[s]));
            if (c == KT - 1) tc_commit(s2u(&s_done));

            if (c + 2 < KT) {
                // MMA(c) reads stage s; wait its completion (round r) before rewrite.
                mbar_wait(s2u(&s_free[s]), (uint32_t)(r & 1));
                load_chunk(c + 2);
            }
        }
    }

    // ---- wait all mma, then epilogue (warps 0-3 read TMEM) ----
    mbar_wait(s2u(&s_done), 0u);
    asm volatile("tcgen05.fence::after_thread_sync;" ::: "memory");

    if (wid < 4) {
        const int m = m0 + wid * 32 + lane;
        const size_t rowbase = (size_t)m * DH + n0;
        #pragma unroll
        for (int cb = 0; cb < 128; cb += 16) {
            uint32_t rz[16], rh[16];
            asm volatile(
                "tcgen05.ld.sync.aligned.32x32b.x16.b32 "
                "{%0,%1,%2,%3,%4,%5,%6,%7,%8,%9,%10,%11,%12,%13,%14,%15}, [%16];"
                : "=r"(rz[0]),"=r"(rz[1]),"=r"(rz[2]),"=r"(rz[3]),
                  "=r"(rz[4]),"=r"(rz[5]),"=r"(rz[6]),"=r"(rz[7]),
                  "=r"(rz[8]),"=r"(rz[9]),"=r"(rz[10]),"=r"(rz[11]),
                  "=r"(rz[12]),"=r"(rz[13]),"=r"(rz[14]),"=r"(rz[15])
                : "r"(tb + cb));
            asm volatile(
                "tcgen05.ld.sync.aligned.32x32b.x16.b32 "
                "{%0,%1,%2,%3,%4,%5,%6,%7,%8,%9,%10,%11,%12,%13,%14,%15}, [%16];"
                : "=r"(rh[0]),"=r"(rh[1]),"=r"(rh[2]),"=r"(rh[3]),
                  "=r"(rh[4]),"=r"(rh[5]),"=r"(rh[6]),"=r"(rh[7]),
                  "=r"(rh[8]),"=r"(rh[9]),"=r"(rh[10]),"=r"(rh[11]),
                  "=r"(rh[12]),"=r"(rh[13]),"=r"(rh[14]),"=r"(rh[15])
                : "r"(tb + 128 + cb));
            asm volatile("tcgen05.wait::ld.sync.aligned;" ::: "memory");
            #pragma unroll
            for (int q = 0; q < 4; q++) {
                float av[4], bv[4];
                #pragma unroll
                for (int j = 0; j < 4; j++) {
                    int idx = q * 4 + j;
                    int n = n0 + cb + idx;
                    float k = __uint_as_float(rz[idx]) + __ldg(&bz[n]);
                    float p = __uint_as_float(rh[idx]) + __ldg(&bh[n]);
                    act(k, p, av[j], bv[j]);
                }
                *(float4*)&Abuf  [rowbase + cb + q*4] = make_float4(av[0], av[1], av[2], av[3]);
                *(float4*)&g_bbuf[rowbase + cb + q*4] = make_float4(bv[0], bv[1], bv[2], bv[3]);
            }
        }
    }

    __syncthreads();
    if (wid == 8) {
        asm volatile("tcgen05.dealloc.cta_group::1.sync.aligned.b32 %0, %1;" :: "r"(tb), "r"(256u));
    }
#endif  // HAS_TC
}

// =====================================================================
// PATH B: legacy mma.sync GEMM — non-'a' targets only; reads blocked layout.
// =====================================================================
#define BM 128
#define BN 64
#define BK 32
#define AST 40
#define STG_ELEMS 20480

#if !HAS_TC
__device__ __forceinline__ void mma_bf16(float d[4], const uint32_t a[4], uint32_t b0, uint32_t b1) {
    asm volatile(
        "mma.sync.aligned.m16n8k16.row.col.f32.bf16.bf16.f32 "
        "{%0,%1,%2,%3},{%4,%5,%6,%7},{%8,%9},{%0,%1,%2,%3};\n"
        : "+f"(d[0]), "+f"(d[1]), "+f"(d[2]), "+f"(d[3])
        : "r"(a[0]), "r"(a[1]), "r"(a[2]), "r"(a[3]), "r"(b0), "r"(b1));
}
#endif

__global__ __launch_bounds__(256, 2)
void gemm_act_legacy(const float* __restrict__ bz, const float* __restrict__ bh,
                     float* __restrict__ Abuf /* = d_out */) {
#if !HAS_TC
    extern __shared__ __nv_bfloat16 sm[];
    const int tid  = threadIdx.x;
    const int lane = tid & 31;
    const int wid  = tid >> 5;
    const int wm   = wid & 3;
    const int wn   = wid >> 2;
    const int g    = lane >> 2;
    const int t    = lane & 3;

    const int n0 = blockIdx.x * BN;
    const int m0 = blockIdx.y * BM;

    float accz[2][4][4], acch[2][4][4];
    #pragma unroll
    for (int i = 0; i < 2; i++)
        #pragma unroll
        for (int j = 0; j < 4; j++)
            #pragma unroll
            for (int r = 0; r < 4; r++) { accz[i][j][r] = 0.f; acch[i][j][r] = 0.f; }

    auto issue = [&](int kt, int buf) {
        int k0 = kt * BK;
        __nv_bfloat16* S = sm + buf * STG_ELEMS;
        #pragma unroll
        for (int i = 0; i < 2; i++) {
            int idx = tid + i * 256;
            int row = idx >> 2;
            int cg  = idx & 3;
            int ke  = k0 + cg * 8;
            cp16(&S[row*AST + cg*8],        g_xhi + blk_off_elem(m0+row, ke));
            cp16(&S[5120 + row*AST + cg*8], g_xlo + blk_off_elem(m0+row, ke));
        }
        {
            int row = tid >> 2;
            int cg  = tid & 3;
            int ke  = k0 + cg * 8;
            size_t go = blk_off_elem(n0+row, ke);
            cp16(&S[10240 + row*AST + cg*8], g_wzhi + go);
            cp16(&S[12800 + row*AST + cg*8], g_wzlo + go);
            cp16(&S[15360 + row*AST + cg*8], g_whhi + go);
            cp16(&S[17920 + row*AST + cg*8], g_whlo + go);
        }
        cp_commit();
    };

    auto ld32 = [&](const __nv_bfloat16* p) -> uint32_t {
        return *(const uint32_t*)p;
    };

    issue(0, 0);
    const int KTL = DIN / BK;
    for (int kt = 0; kt < KTL; kt++) {
        int buf = kt & 1;
        if (kt + 1 < KTL) { issue(kt + 1, buf ^ 1); cp_wait<1>(); }
        else              { cp_wait<0>(); }
        __syncthreads();
        const __nv_bfloat16* S = sm + buf * STG_ELEMS;
        #pragma unroll
        for (int ks = 0; ks < 2; ks++) {
            const int kb = ks * 16;
            uint32_t ahi[2][4], alo[2][4];
            #pragma unroll
            for (int mf = 0; mf < 2; mf++) {
                int r = wm*32 + mf*16;
                const __nv_bfloat16* A0 = S + (r+g  )*AST + kb + 2*t;
                const __nv_bfloat16* A1 = S + (r+g+8)*AST + kb + 2*t;
                ahi[mf][0] = ld32(A0);     ahi[mf][1] = ld32(A1);
                ahi[mf][2] = ld32(A0 + 8); ahi[mf][3] = ld32(A1 + 8);
                alo[mf][0] = ld32(A0 + 5120);     alo[mf][1] = ld32(A1 + 5120);
                alo[mf][2] = ld32(A0 + 5120 + 8); alo[mf][3] = ld32(A1 + 5120 + 8);
            }
            #pragma unroll
            for (int nf = 0; nf < 4; nf++) {
                int c = wn*32 + nf*8 + g;
                const __nv_bfloat16* B = S + c*AST + kb + 2*t;
                uint32_t zh0 = ld32(B + 10240), zh1 = ld32(B + 10240 + 8);
                uint32_t zl0 = ld32(B + 12800), zl1 = ld32(B + 12800 + 8);
                uint32_t hh0 = ld32(B + 15360), hh1 = ld32(B + 15360 + 8);
                uint32_t hl0 = ld32(B + 17920), hl1 = ld32(B + 17920 + 8);
                #pragma unroll
                for (int mf = 0; mf < 2; mf++) {
                    mma_bf16(accz[mf][nf], ahi[mf], zh0, zh1);
                    mma_bf16(accz[mf][nf], alo[mf], zh0, zh1);
                    mma_bf16(accz[mf][nf], ahi[mf], zl0, zl1);
                    mma_bf16(acch[mf][nf], ahi[mf], hh0, hh1);
                    mma_bf16(acch[mf][nf], alo[mf], hh0, hh1);
                    mma_bf16(acch[mf][nf], ahi[mf], hl0, hl1);
                }
            }
        }
        __syncthreads();
    }

    #pragma unroll
    for (int mf = 0; mf < 2; mf++) {
        #pragma unroll
        for (int nf = 0; nf < 4; nf++) {
            int m = m0 + wm*32 + mf*16 + g;
            int n = n0 + wn*32 + nf*8 + 2*t;
            float bz0 = bz[n], bz1 = bz[n+1];
            float bh0 = bh[n], bh1 = bh[n+1];
            float a0,b0v,a1,b1v,a2,b2v,a3,b3v;
            act(accz[mf][nf][0] + bz0, acch[mf][nf][0] + bh0, a0, b0v);
            act(accz[mf][nf][1] + bz1, acch[mf][nf][1] + bh1, a1, b1v);
            act(accz[mf][nf][2] + bz0, acch[mf][nf][2] + bh0, a2, b2v);
            act(accz[mf][nf][3] + bz1, acch[mf][nf][3] + bh1, a3, b3v);
            size_t o0 = (size_t)m     * DH + n;
            size_t o1 = (size_t)(m+8) * DH + n;
            *(float2*)&Abuf[o0]   = make_float2(a0, a1);
            *(float2*)&g_bbuf[o0] = make_float2(b0v, b1v);
            *(float2*)&Abuf[o1]   = make_float2(a2, a3);
            *(float2*)&g_bbuf[o1] = make_float2(b2v, b3v);
        }
    }
#endif  // !HAS_TC
}

// ================= Sequential scan: h_t = a_t*h_{t-1} + b_t (fp64 carry) ======
// BYTE-EXACT round-11 scan (passed with the tc pipeline).
#define SCT 32
#define NST 3
#define SCH 64

__global__ __launch_bounds__(64)
void scan_kernel(float* __restrict__ out) {
    extern __shared__ float sms[];
    const int tid = threadIdx.x;
    const int b   = blockIdx.x >> 4;
    const int h0  = (blockIdx.x & 15) * SCH;
    const size_t base = (size_t)b * SEQ * DH + h0;
    const float* Asrc = out;
    const float* Bsrc = g_bbuf;

    auto issue = [&](int s) {
        int slot = s % NST;
        int t0 = s * SCT;
        float* sa   = &sms[(slot*2 + 0) * SCT * SCH];
        float* sbuf = &sms[(slot*2 + 1) * SCT * SCH];
        #pragma unroll
        for (int j = 0; j < 8; j++) {
            int idx = tid + j * 64;
            int tt  = idx >> 4;
            int c   = idx & 15;
            cp16(&sa[tt*SCH + c*4],   &Asrc[base + (size_t)(t0+tt)*DH + c*4]);
            cp16(&sbuf[tt*SCH + c*4], &Bsrc[base + (size_t)(t0+tt)*DH + c*4]);
        }
        cp_commit();
    };

    issue(0); issue(1);
    double h = 0.5;
    const int NS = SEQ / SCT;
    for (int s = 0; s < NS; s++) {
        cp_wait<1>();
        __syncthreads();
        int slot = s % NST;
        const float* sa   = &sms[(slot*2 + 0) * SCT * SCH];
        const float* sbuf = &sms[(slot*2 + 1) * SCT * SCH];
        int t0 = s * SCT;
        #pragma unroll
        for (int tt = 0; tt < SCT; tt++) {
            double a  = (double)sa[tt*SCH + tid];
            double bb = (double)sbuf[tt*SCH + tid];
            h = fma(a, h, bb);
            out[base + (size_t)(t0+tt)*DH + tid] = (float)h;
        }
        __syncthreads();
        if (s + 2 < NS) issue(s + 2);
    }
}

// ================= launch =================
extern "C" void kernel_launch(void* const* d_in, const int* in_sizes, int n_in,
                              void* d_out, int out_size) {
    // Identify inputs BY SIZE: 33554432 -> x ; 1048576 -> Wz then Wh ; 1024 -> bz then bh.
    const float* x = nullptr; const float* Wz = nullptr; const float* Wh = nullptr;
    const float* bz = nullptr; const float* bh = nullptr;
    for (int i = 0; i < n_in; i++) {
        int sz = in_sizes[i];
        const float* p = (const float*)d_in[i];
        if      (sz == M_TOT * DIN) { x = p; }
        else if (sz == DH * DIN)    { if (!Wz) Wz = p; else Wh = p; }
        else if (sz == DH)          { if (!bz) bz = p; else bh = p; }
    }
    if (!x || !Wz || !Wh || !bz || !bh) {
        x  = (const float*)d_in[0];
        Wz = (const float*)d_in[1];
        bz = (const float*)d_in[2];
        Wh = (const float*)d_in[3];
        bh = (const float*)d_in[4];
    }
    float* out = (float*)d_out;

    // 1) split fp32 -> blocked-swizzled bf16 hi/lo (16B granules)
    {
        int ngx = M_TOT * DIN / 8;
        split_kernel<<<(ngx + 255) / 256, 256>>>(x, 0, ngx);
        int ngw = DH * DIN / 8;
        split_kernel<<<(ngw + 255) / 256, 256>>>(Wz, 1, ngw);
        split_kernel<<<(ngw + 255) / 256, 256>>>(Wh, 2, ngw);
    }

    // 2) dual GEMM + activation — both variants launched; exactly one has a body.
    cudaFuncSetAttribute(gemm_act_tc, cudaFuncAttributeMaxDynamicSharedMemorySize, DSMEM_TC);
    dim3 tgrid(DH / 128, M_TOT / 128);   // (8, 256)
    gemm_act_tc<<<tgrid, 288, DSMEM_TC>>>(bz, bh, out);

    cudaFuncSetAttribute(gemm_act_legacy, cudaFuncAttributeMaxDynamicSharedMemorySize,
                         2 * STG_ELEMS * (int)sizeof(__nv_bfloat16));
    dim3 lgrid(DH / BN, M_TOT / BM);     // (16, 256)
    gemm_act_legacy<<<lgrid, 256, 2 * STG_ELEMS * sizeof(__nv_bfloat16)>>>(bz, bh, out);

    // 3) sequential scan (reads a from out, overwrites with h)
    scan_kernel<<<BATCH * (DH / SCH), SCH, NST * 2 * SCT * SCH * sizeof(float)>>>(out);
}